// round 6
// baseline (speedup 1.0000x reference)
#include <cuda_runtime.h>
#include <cuda_bf16.h>
#include <cstdint>

// Shapes (fixed): x [4,8,1024,512] -> M=32768 rows, K=512; W1,W2 [512,512].
#define MTOT  32768
#define MPERT 8192
#define KD    512
#define ND    512
#define NCHAN (MPERT * ND)
#define FLAG_CAP 2097152
#define MARGIN 0.02f

// ---------------- scratch (no cudaMalloc allowed) ----------------
__device__ __align__(16) __nv_bfloat16 g_x0[(size_t)MTOT * KD];
__device__ __align__(16) __nv_bfloat16 g_w10[KD * ND];
__device__ __align__(16) __nv_bfloat16 g_w11[KD * ND];
__device__ __align__(16) __nv_bfloat16 g_w20[KD * ND];
__device__ __align__(16) __nv_bfloat16 g_w21[KD * ND];
__device__ __align__(16) __nv_bfloat16 g_s[(size_t)MTOT * ND];
__device__ int g_flags[FLAG_CAP];
__device__ int g_flag_count;

// ---------------- base-target PTX helpers (sm_80-era only) -----------------
__device__ __forceinline__ uint32_t smem_u32(const void* p) {
    uint32_t a;
    asm("{ .reg .u64 t; cvta.to.shared.u64 t, %1; cvt.u32.u64 %0, t; }"
        : "=r"(a) : "l"(p));
    return a;
}
__device__ __forceinline__ void cp_async16(uint32_t dst, const void* src) {
    asm volatile("cp.async.cg.shared.global [%0], [%1], 16;"
                 :: "r"(dst), "l"(src) : "memory");
}
__device__ __forceinline__ void cp_commit() {
    asm volatile("cp.async.commit_group;" ::: "memory");
}
template <int N>
__device__ __forceinline__ void cp_wait() {
    asm volatile("cp.async.wait_group %0;" :: "n"(N) : "memory");
}
__device__ __forceinline__ void ldsm_x4(uint32_t& r0, uint32_t& r1,
                                        uint32_t& r2, uint32_t& r3, uint32_t a) {
    asm volatile("ldmatrix.sync.aligned.m8n8.x4.shared.b16 {%0,%1,%2,%3}, [%4];"
                 : "=r"(r0), "=r"(r1), "=r"(r2), "=r"(r3) : "r"(a));
}
__device__ __forceinline__ void mma16816(float& c0, float& c1, float& c2, float& c3,
                                         uint32_t a0, uint32_t a1, uint32_t a2, uint32_t a3,
                                         uint32_t b0, uint32_t b1) {
    asm volatile(
        "mma.sync.aligned.m16n8k16.row.col.f32.bf16.bf16.f32 "
        "{%0,%1,%2,%3}, {%4,%5,%6,%7}, {%8,%9}, {%0,%1,%2,%3};"
        : "+f"(c0), "+f"(c1), "+f"(c2), "+f"(c3)
        : "r"(a0), "r"(a1), "r"(a2), "r"(a3), "r"(b0), "r"(b1));
}

// ---------------- dual-B bf16 HMMA GEMM:  C = A @ B0^T + A @ B1^T -----------
// CTA 128x128, BK=64, 8 warps @ 64x32. Stage = A(16K)+B0(16K)+B1(16K) = 48KB,
// 2 stages. FUSED: GEMM1 with t-interleaved M rows + in-register LIF epilogue
// writing bf16 spikes + near-threshold flags. Non-fused: plain fp32 C store.
struct GArgs {
    const __nv_bfloat16* A;
    const __nv_bfloat16* B0;
    const __nv_bfloat16* B1;
    void* C;
};

#define STAGE_BYTES 49152
#define SMEM_DYN    98304

template <bool FUSED>
__global__ void __launch_bounds__(256, 2) hmma_gemm(GArgs args)
{
    extern __shared__ char dynsmem[];
    const uint32_t sb = smem_u32(dynsmem);

    const int tid   = threadIdx.x;
    const int lane  = tid & 31;
    const int warp  = tid >> 5;
    const int wm    = warp >> 2;
    const int wn    = warp & 3;
    const int tileN = blockIdx.x;          // fast dim -> A tile L2 reuse
    const int tileM = blockIdx.y;

    const int ldRow = tid >> 1;
    const int ldC0  = (tid & 1) * 4;
    const int lrow  = lane & 15;
    const int lsel  = lane >> 4;

    // global A row for this thread's smem row (FUSED: t-interleaved mapping)
    size_t arowOff;
    if (FUSED) {
        int t   = (ldRow >> 3) & 3;
        int bno = (ldRow & 7) | ((ldRow >> 5) << 3);
        arowOff = ((size_t)t * MPERT + tileM * 32 + bno) * KD;
    } else {
        arowOff = ((size_t)tileM * 128 + ldRow) * KD;
    }
    const size_t browOff = ((size_t)tileN * 128 + ldRow) * KD;

    float acc[4][4][4];
    #pragma unroll
    for (int i = 0; i < 4; ++i)
        #pragma unroll
        for (int j = 0; j < 4; ++j)
            #pragma unroll
            for (int q = 0; q < 4; ++q) acc[i][j][q] = 0.f;

    auto load_stage = [&](int it) {
        const int k0 = it * 64;
        const uint32_t base  = sb + (it & 1) * STAGE_BYTES;
        const uint32_t swrow = (uint32_t)(ldRow & 7);
        #pragma unroll
        for (int c = 0; c < 4; ++c) {
            uint32_t ch = (uint32_t)(ldC0 + c);
            uint32_t sw = (ch ^ swrow) * 16u + (uint32_t)ldRow * 128u;
            cp_async16(base + sw,          args.A  + arowOff + k0 + ch * 8);
            cp_async16(base + 16384 + sw,  args.B0 + browOff + k0 + ch * 8);
            cp_async16(base + 32768 + sw,  args.B1 + browOff + k0 + ch * 8);
        }
        cp_commit();
    };

    uint32_t a[4][4], b[2][4][2];

    auto load_a = [&](uint32_t ab, int ks) {
        #pragma unroll
        for (int mt = 0; mt < 4; ++mt) {
            int row = wm * 64 + mt * 16 + lrow;
            uint32_t ch = (uint32_t)(ks * 2 + lsel);
            uint32_t ad = ab + (uint32_t)row * 128u + ((ch ^ (uint32_t)(row & 7)) * 16u);
            ldsm_x4(a[mt][0], a[mt][1], a[mt][2], a[mt][3], ad);
        }
    };
    auto load_b = [&](uint32_t bb, int ks, int half) {
        #pragma unroll
        for (int nt2 = 0; nt2 < 2; ++nt2) {
            int row = wn * 32 + nt2 * 16 + lrow;
            uint32_t ch = (uint32_t)(ks * 2 + lsel);
            uint32_t bd = bb + (uint32_t)row * 128u + ((ch ^ (uint32_t)(row & 7)) * 16u);
            uint32_t r0, r1, r2, r3;
            ldsm_x4(r0, r1, r2, r3, bd);
            b[half][nt2 * 2 + 0][0] = r0; b[half][nt2 * 2 + 1][0] = r1;
            b[half][nt2 * 2 + 0][1] = r2; b[half][nt2 * 2 + 1][1] = r3;
        }
    };

    load_stage(0);

    for (int it = 0; it < 8; ++it) {
        if (it < 7) load_stage(it + 1);
        else cp_commit();
        cp_wait<1>();
        __syncthreads();

        const uint32_t ab = sb + (it & 1) * STAGE_BYTES;

        #pragma unroll
        for (int ks = 0; ks < 4; ++ks) {
            load_a(ab, ks);
            load_b(ab + 16384, ks, 0);
            load_b(ab + 32768, ks, 1);
            #pragma unroll
            for (int h2 = 0; h2 < 2; ++h2)
                #pragma unroll
                for (int mt = 0; mt < 4; ++mt)
                    #pragma unroll
                    for (int nt = 0; nt < 4; ++nt)
                        mma16816(acc[mt][nt][0], acc[mt][nt][1],
                                 acc[mt][nt][2], acc[mt][nt][3],
                                 a[mt][0], a[mt][1], a[mt][2], a[mt][3],
                                 b[h2][nt][0], b[h2][nt][1]);
        }
        __syncthreads();
    }
    cp_wait<0>();

    if constexpr (!FUSED) {
        float* __restrict__ C = (float*)args.C;
        const int rbase = tileM * 128 + wm * 64 + (lane >> 2);
        const int cbase = tileN * 128 + wn * 32 + (lane & 3) * 2;
        #pragma unroll
        for (int mt = 0; mt < 4; ++mt) {
            #pragma unroll
            for (int nt = 0; nt < 4; ++nt) {
                int r0 = rbase + mt * 16;
                int cc = cbase + nt * 8;
                *reinterpret_cast<float2*>(C + (size_t)r0 * ND + cc) =
                    make_float2(acc[mt][nt][0], acc[mt][nt][1]);
                *reinterpret_cast<float2*>(C + (size_t)(r0 + 8) * ND + cc) =
                    make_float2(acc[mt][nt][2], acc[mt][nt][3]);
            }
        }
    } else {
        // LIF epilogue. Thread fragment rows r = wm*64 + mt*16 + 8k + l4 map to
        //   t = (k + 2*mt) & 3,  bn_local = l4 + 8*(2*wm + (mt>>1))
        // so acc[2g + (t>>1)][nt][(t&1)*2 + cc] is h_t of channel
        //   (bn = tileM*32 + l4 + 8*(2wm+g),  c = cbase + nt*8 + cc).
        __nv_bfloat16* __restrict__ s = (__nv_bfloat16*)args.C;
        const int l4 = lane >> 2;
        const int c0base = tileN * 128 + wn * 32 + (lane & 3) * 2;
        #pragma unroll
        for (int nt = 0; nt < 4; ++nt) {
            #pragma unroll
            for (int g = 0; g < 2; ++g) {
                const int bn = tileM * 32 + l4 + 8 * (2 * wm + g);
                const int c0 = c0base + nt * 8;
                float v0 = 0.f, v1 = 0.f;
                bool r0 = false, r1 = false;
                uint32_t pk[4];
                #pragma unroll
                for (int t = 0; t < 4; ++t) {
                    const int mt = 2 * g + (t >> 1);
                    const int q  = (t & 1) * 2;
                    float h0 = acc[mt][nt][q + 0];
                    float h1 = acc[mt][nt][q + 1];
                    v0 = v0 + (h0 - v0) / 2.0f;
                    v1 = v1 + (h1 - v1) / 2.0f;
                    r0 |= (fabsf(v0 - 1.0f) < MARGIN);
                    r1 |= (fabsf(v1 - 1.0f) < MARGIN);
                    bool f0 = (v0 >= 1.0f), f1 = (v1 >= 1.0f);
                    pk[t] = (f0 ? 0x3F80u : 0u) | ((f1 ? 0x3F80u : 0u) << 16);
                    if (f0) v0 = 0.f;
                    if (f1) v1 = 0.f;
                }
                #pragma unroll
                for (int t = 0; t < 4; ++t)
                    *reinterpret_cast<uint32_t*>(
                        s + ((size_t)t * MPERT + bn) * ND + c0) = pk[t];
                if (r0) {
                    int slot = atomicAdd(&g_flag_count, 1);
                    if (slot < FLAG_CAP) g_flags[slot] = bn * ND + c0;
                }
                if (r1) {
                    int slot = atomicAdd(&g_flag_count, 1);
                    if (slot < FLAG_CAP) g_flags[slot] = bn * ND + c0 + 1;
                }
            }
        }
    }
}

// ---------------- x -> bf16 convert (also zeroes flag counter) -------------
__global__ void __launch_bounds__(256) conv_x_kernel(
    const float4* __restrict__ in, uint2* __restrict__ o0, int n4)
{
    if (blockIdx.x == 0 && threadIdx.x == 0) g_flag_count = 0;
    int i = blockIdx.x * blockDim.x + threadIdx.x;
    if (i >= n4) return;
    float4 v = in[i];
    unsigned short a0 = __bfloat16_as_ushort(__float2bfloat16_rn(v.x));
    unsigned short a1 = __bfloat16_as_ushort(__float2bfloat16_rn(v.y));
    unsigned short a2 = __bfloat16_as_ushort(__float2bfloat16_rn(v.z));
    unsigned short a3 = __bfloat16_as_ushort(__float2bfloat16_rn(v.w));
    o0[i] = make_uint2((uint32_t)a0 | ((uint32_t)a1 << 16),
                       (uint32_t)a2 | ((uint32_t)a3 << 16));
}

// ---------------- fp32 -> bf16 2-split (weights) ----------------
__global__ void __launch_bounds__(256) split2_kernel(
    const float4* __restrict__ in, uint2* __restrict__ o0,
    uint2* __restrict__ o1, int n4)
{
    int i = blockIdx.x * blockDim.x + threadIdx.x;
    if (i >= n4) return;
    float4 v = in[i];
    float f[4] = {v.x, v.y, v.z, v.w};
    unsigned short a[4], b[4];
    #pragma unroll
    for (int j = 0; j < 4; ++j) {
        __nv_bfloat16 h0 = __float2bfloat16_rn(f[j]);
        float r = f[j] - __bfloat162float(h0);
        __nv_bfloat16 h1 = __float2bfloat16_rn(r);
        a[j] = __bfloat16_as_ushort(h0);
        b[j] = __bfloat16_as_ushort(h1);
    }
    o0[i] = make_uint2((uint32_t)a[0] | ((uint32_t)a[1] << 16),
                       (uint32_t)a[2] | ((uint32_t)a[3] << 16));
    o1[i] = make_uint2((uint32_t)b[0] | ((uint32_t)b[1] << 16),
                       (uint32_t)b[2] | ((uint32_t)b[3] << 16));
}

// ---------------- exact fix-up: bit-identical sequential fp32 dot ----------
__global__ void __launch_bounds__(128) fixup_kernel(
    const float* __restrict__ x, const float* __restrict__ W1,
    __nv_bfloat16* __restrict__ s)
{
    int count = g_flag_count;
    if (count > FLAG_CAP) count = FLAG_CAP;
    for (int j = blockIdx.x * blockDim.x + threadIdx.x; j < count;
         j += gridDim.x * blockDim.x) {
        const int idx = g_flags[j];
        const int bn  = idx >> 9;
        const int c   = idx & 511;
        const float4* w = reinterpret_cast<const float4*>(W1 + (size_t)c * KD);
        float v = 0.0f;
        #pragma unroll 1
        for (int t = 0; t < 4; ++t) {
            const float4* xr = reinterpret_cast<const float4*>(
                x + ((size_t)t * MPERT + bn) * KD);
            float acc = 0.0f;
            // single accumulator, ascending k: bit-identical to reference
            for (int k4 = 0; k4 < KD / 4; ++k4) {
                float4 xv = xr[k4];
                float4 wv = w[k4];
                acc = fmaf(xv.x, wv.x, acc);
                acc = fmaf(xv.y, wv.y, acc);
                acc = fmaf(xv.z, wv.z, acc);
                acc = fmaf(xv.w, wv.w, acc);
            }
            v = v + (acc - v) / 2.0f;
            bool fire = (v >= 1.0f);
            s[(size_t)t * NCHAN + idx] =
                __ushort_as_bfloat16(fire ? (unsigned short)0x3F80 : (unsigned short)0);
            if (fire) v = 0.0f;
        }
    }
}

// ---------------- launch ----------------
extern "C" void kernel_launch(void* const* d_in, const int* in_sizes, int n_in,
                              void* d_out, int out_size)
{
    const float* x  = (const float*)d_in[0];
    const float* W1 = (const float*)d_in[1];
    const float* W2 = (const float*)d_in[2];
    float* out = (float*)d_out;

    __nv_bfloat16 *x0, *w10, *w11, *w20, *w21, *s;
    cudaGetSymbolAddress((void**)&x0,  g_x0);
    cudaGetSymbolAddress((void**)&w10, g_w10);
    cudaGetSymbolAddress((void**)&w11, g_w11);
    cudaGetSymbolAddress((void**)&w20, g_w20);
    cudaGetSymbolAddress((void**)&w21, g_w21);
    cudaGetSymbolAddress((void**)&s,   g_s);

    cudaFuncSetAttribute(hmma_gemm<true>,
                         cudaFuncAttributeMaxDynamicSharedMemorySize, SMEM_DYN);
    cudaFuncSetAttribute(hmma_gemm<false>,
                         cudaFuncAttributeMaxDynamicSharedMemorySize, SMEM_DYN);

    conv_x_kernel<<<(MTOT * KD / 4) / 256, 256>>>(
        (const float4*)x, (uint2*)x0, MTOT * KD / 4);
    split2_kernel<<<(KD * ND / 4) / 256, 256>>>(
        (const float4*)W1, (uint2*)w10, (uint2*)w11, KD * ND / 4);
    split2_kernel<<<(KD * ND / 4) / 256, 256>>>(
        (const float4*)W2, (uint2*)w20, (uint2*)w21, KD * ND / 4);

    // GEMM1 (fused): h = x0@W1^T via (x0*w10 + x0*w11); LIF + flags in epilogue
    GArgs g1 = {x0, w10, w11, (void*)s};
    hmma_gemm<true><<<dim3(4, 256), 256, SMEM_DYN>>>(g1);

    // exact fix-up of near-threshold channels (bit-identical to reference)
    fixup_kernel<<<256, 128>>>(x, W1, s);

    // GEMM2: out = s@W2^T via (s*w20 + s*w21); spikes exact in bf16
    GArgs g2 = {s, w20, w21, (void*)out};
    hmma_gemm<false><<<dim3(4, 256), 256, SMEM_DYN>>>(g2);
}

// round 7
// speedup vs baseline: 1.3174x; 1.3174x over previous
#include <cuda_runtime.h>
#include <cuda_bf16.h>
#include <cstdint>

// Shapes (fixed): x [4,8,1024,512] -> M=32768 rows, K=512; W1,W2 [512,512].
#define MTOT  32768
#define MPERT 8192
#define KD    512
#define ND    512
#define NCHAN (MPERT * ND)
#define FLAG_CAP 262144
#define MARGIN 1e-4f

// ---------------- scratch (no cudaMalloc allowed) ----------------
__device__ __align__(16) __nv_bfloat16 g_x0[(size_t)MTOT * KD];
__device__ __align__(16) __nv_bfloat16 g_x1[(size_t)MTOT * KD];
__device__ __align__(16) __nv_bfloat16 g_w10[KD * ND];
__device__ __align__(16) __nv_bfloat16 g_w11[KD * ND];
__device__ __align__(16) __nv_bfloat16 g_w20[KD * ND];
__device__ __align__(16) __nv_bfloat16 g_w21[KD * ND];
__device__ __align__(16) __nv_bfloat16 g_s[(size_t)MTOT * ND];
__device__ int g_flags[FLAG_CAP];
__device__ int g_flag_count;

// ---------------- base-target PTX helpers (sm_80-era only) -----------------
__device__ __forceinline__ uint32_t smem_u32(const void* p) {
    uint32_t a;
    asm("{ .reg .u64 t; cvta.to.shared.u64 t, %1; cvt.u32.u64 %0, t; }"
        : "=r"(a) : "l"(p));
    return a;
}
__device__ __forceinline__ void cp_async16(uint32_t dst, const void* src) {
    asm volatile("cp.async.cg.shared.global [%0], [%1], 16;"
                 :: "r"(dst), "l"(src) : "memory");
}
__device__ __forceinline__ void cp_commit() {
    asm volatile("cp.async.commit_group;" ::: "memory");
}
template <int N>
__device__ __forceinline__ void cp_wait() {
    asm volatile("cp.async.wait_group %0;" :: "n"(N) : "memory");
}
__device__ __forceinline__ void ldsm_x4(uint32_t& r0, uint32_t& r1,
                                        uint32_t& r2, uint32_t& r3, uint32_t a) {
    asm volatile("ldmatrix.sync.aligned.m8n8.x4.shared.b16 {%0,%1,%2,%3}, [%4];"
                 : "=r"(r0), "=r"(r1), "=r"(r2), "=r"(r3) : "r"(a));
}
__device__ __forceinline__ void mma16816(float& c0, float& c1, float& c2, float& c3,
                                         uint32_t a0, uint32_t a1, uint32_t a2, uint32_t a3,
                                         uint32_t b0, uint32_t b1) {
    asm volatile(
        "mma.sync.aligned.m16n8k16.row.col.f32.bf16.bf16.f32 "
        "{%0,%1,%2,%3}, {%4,%5,%6,%7}, {%8,%9}, {%0,%1,%2,%3};"
        : "+f"(c0), "+f"(c1), "+f"(c2), "+f"(c3)
        : "r"(a0), "r"(a1), "r"(a2), "r"(a3), "r"(b0), "r"(b1));
}

// ============================================================================
// GEMM1 (fused): h = A0@B0^T + A0@B1^T + A1@B0^T, LIF + flags in epilogue.
// 512 threads (16 warps, 4x4), CTA tile 128x128, BK=64.
// Stage = A0+A1+B0+B1 = 64KB, 3 stages = 192KB, 1 CTA/SM.
// M rows are t-interleaved: smem row r <-> (t=(r>>3)&3, bn=tileM*32+(r&7)+8*(r>>5))
// ============================================================================
#define SMEM1 196608

__global__ void __launch_bounds__(512, 1) gemm1_fused(
    const __nv_bfloat16* __restrict__ A0, const __nv_bfloat16* __restrict__ A1,
    const __nv_bfloat16* __restrict__ B0, const __nv_bfloat16* __restrict__ B1,
    __nv_bfloat16* __restrict__ s)
{
    extern __shared__ char dynsmem[];
    const uint32_t sb = smem_u32(dynsmem);

    const int tid  = threadIdx.x;
    const int lane = tid & 31;
    const int warp = tid >> 5;
    const int wm   = warp >> 2;            // 0..3 (32 M rows each)
    const int wn   = warp & 3;             // 0..3 (32 N cols each)
    const int tileN = blockIdx.x;          // 0..3 (fast -> A L2 reuse)
    const int tileM = blockIdx.y;          // 0..255

    const int ldRow = tid >> 2;            // 0..127
    const int ldC0  = (tid & 3) * 2;       // 2 chunks per tile per thread
    const int lrow  = lane & 15;
    const int lsel  = lane >> 4;

    // t-interleaved A row
    const int t_   = (ldRow >> 3) & 3;
    const int bno  = (ldRow & 7) | ((ldRow >> 5) << 3);
    const size_t arow = ((size_t)t_ * MPERT + tileM * 32 + bno) * KD;
    const size_t brow = ((size_t)tileN * 128 + ldRow) * KD;

    float acc[2][4][4];
    #pragma unroll
    for (int i = 0; i < 2; ++i)
        #pragma unroll
        for (int j = 0; j < 4; ++j)
            #pragma unroll
            for (int q = 0; q < 4; ++q) acc[i][j][q] = 0.f;

    auto load_stage = [&](int it) {
        const int k0 = it * 64;
        const uint32_t base = sb + (uint32_t)(it % 3) * 65536u;
        const uint32_t swr  = (uint32_t)(ldRow & 7);
        #pragma unroll
        for (int c = 0; c < 2; ++c) {
            uint32_t ch = (uint32_t)(ldC0 + c);
            uint32_t sw = (ch ^ swr) * 16u + (uint32_t)ldRow * 128u;
            cp_async16(base + sw,          A0 + arow + k0 + ch * 8);
            cp_async16(base + 16384 + sw,  A1 + arow + k0 + ch * 8);
            cp_async16(base + 32768 + sw,  B0 + brow + k0 + ch * 8);
            cp_async16(base + 49152 + sw,  B1 + brow + k0 + ch * 8);
        }
        cp_commit();
    };

    load_stage(0);
    load_stage(1);

    uint32_t a0f[2][4], a1f[2][4], b0f[4][2], b1f[4][2];

    auto load_afrag = [&](uint32_t tb, int ks, uint32_t (&f)[2][4]) {
        #pragma unroll
        for (int mt = 0; mt < 2; ++mt) {
            int row = wm * 32 + mt * 16 + lrow;
            uint32_t ch = (uint32_t)(ks * 2 + lsel);
            uint32_t ad = tb + (uint32_t)row * 128u + ((ch ^ (uint32_t)(row & 7)) * 16u);
            ldsm_x4(f[mt][0], f[mt][1], f[mt][2], f[mt][3], ad);
        }
    };
    auto load_bfrag = [&](uint32_t tb, int ks, uint32_t (&f)[4][2]) {
        #pragma unroll
        for (int nt2 = 0; nt2 < 2; ++nt2) {
            int row = wn * 32 + nt2 * 16 + lrow;
            uint32_t ch = (uint32_t)(ks * 2 + lsel);
            uint32_t bd = tb + (uint32_t)row * 128u + ((ch ^ (uint32_t)(row & 7)) * 16u);
            uint32_t r0, r1, r2, r3;
            ldsm_x4(r0, r1, r2, r3, bd);
            f[nt2 * 2 + 0][0] = r0; f[nt2 * 2 + 1][0] = r1;
            f[nt2 * 2 + 0][1] = r2; f[nt2 * 2 + 1][1] = r3;
        }
    };

    for (int it = 0; it < 8; ++it) {
        if (it + 2 < 8) load_stage(it + 2);
        else cp_commit();
        cp_wait<2>();
        __syncthreads();

        const uint32_t base = sb + (uint32_t)(it % 3) * 65536u;

        #pragma unroll
        for (int ks = 0; ks < 4; ++ks) {
            load_afrag(base,          ks, a0f);
            load_afrag(base + 16384,  ks, a1f);
            load_bfrag(base + 32768,  ks, b0f);
            load_bfrag(base + 49152,  ks, b1f);
            #pragma unroll
            for (int mt = 0; mt < 2; ++mt)
                #pragma unroll
                for (int nt = 0; nt < 4; ++nt)
                    mma16816(acc[mt][nt][0], acc[mt][nt][1],
                             acc[mt][nt][2], acc[mt][nt][3],
                             a0f[mt][0], a0f[mt][1], a0f[mt][2], a0f[mt][3],
                             b0f[nt][0], b0f[nt][1]);
            #pragma unroll
            for (int mt = 0; mt < 2; ++mt)
                #pragma unroll
                for (int nt = 0; nt < 4; ++nt)
                    mma16816(acc[mt][nt][0], acc[mt][nt][1],
                             acc[mt][nt][2], acc[mt][nt][3],
                             a0f[mt][0], a0f[mt][1], a0f[mt][2], a0f[mt][3],
                             b1f[nt][0], b1f[nt][1]);
            #pragma unroll
            for (int mt = 0; mt < 2; ++mt)
                #pragma unroll
                for (int nt = 0; nt < 4; ++nt)
                    mma16816(acc[mt][nt][0], acc[mt][nt][1],
                             acc[mt][nt][2], acc[mt][nt][3],
                             a1f[mt][0], a1f[mt][1], a1f[mt][2], a1f[mt][3],
                             b0f[nt][0], b0f[nt][1]);
        }
        __syncthreads();
    }
    cp_wait<0>();

    // LIF epilogue. Fragment row r = wm*32 + mt*16 + k*8 + (lane>>2):
    //   t = 2*mt + k,  bn = tileM*32 + (lane>>2) + 8*wm
    // so h_t of channel cc is acc[t>>1][nt][(t&1)*2 + cc].
    {
        const int bn = tileM * 32 + (lane >> 2) + 8 * wm;
        const int c0base = tileN * 128 + wn * 32 + (lane & 3) * 2;
        #pragma unroll
        for (int nt = 0; nt < 4; ++nt) {
            const int c0 = c0base + nt * 8;
            float v0 = 0.f, v1 = 0.f;
            bool r0 = false, r1 = false;
            uint32_t pk[4];
            #pragma unroll
            for (int t = 0; t < 4; ++t) {
                const int mt = t >> 1;
                const int q  = (t & 1) * 2;
                float h0 = acc[mt][nt][q + 0];
                float h1 = acc[mt][nt][q + 1];
                v0 = v0 + (h0 - v0) / 2.0f;
                v1 = v1 + (h1 - v1) / 2.0f;
                r0 |= (fabsf(v0 - 1.0f) < MARGIN);
                r1 |= (fabsf(v1 - 1.0f) < MARGIN);
                bool f0 = (v0 >= 1.0f), f1 = (v1 >= 1.0f);
                pk[t] = (f0 ? 0x3F80u : 0u) | ((f1 ? 0x3F80u : 0u) << 16);
                if (f0) v0 = 0.f;
                if (f1) v1 = 0.f;
            }
            #pragma unroll
            for (int t = 0; t < 4; ++t)
                *reinterpret_cast<uint32_t*>(
                    s + ((size_t)t * MPERT + bn) * ND + c0) = pk[t];
            if (r0) {
                int slot = atomicAdd(&g_flag_count, 1);
                if (slot < FLAG_CAP) g_flags[slot] = bn * ND + c0;
            }
            if (r1) {
                int slot = atomicAdd(&g_flag_count, 1);
                if (slot < FLAG_CAP) g_flags[slot] = bn * ND + c0 + 1;
            }
        }
    }
}

// ============================================================================
// GEMM2: out = A@B0^T + A@B1^T (dual-B, round-6 kernel, proven)
// 256 threads (8 warps @ 64x32), CTA 128x128, 48KB x 2 stages.
// ============================================================================
#define STAGE2 49152
#define SMEM2  98304

__global__ void __launch_bounds__(256, 2) gemm2_kernel(
    const __nv_bfloat16* __restrict__ A, const __nv_bfloat16* __restrict__ B0,
    const __nv_bfloat16* __restrict__ B1, float* __restrict__ C)
{
    extern __shared__ char dynsmem[];
    const uint32_t sb = smem_u32(dynsmem);

    const int tid   = threadIdx.x;
    const int lane  = tid & 31;
    const int warp  = tid >> 5;
    const int wm    = warp >> 2;
    const int wn    = warp & 3;
    const int tileN = blockIdx.x;
    const int tileM = blockIdx.y;

    const int ldRow = tid >> 1;
    const int ldC0  = (tid & 1) * 4;
    const int lrow  = lane & 15;
    const int lsel  = lane >> 4;

    const size_t arow = ((size_t)tileM * 128 + ldRow) * KD;
    const size_t brow = ((size_t)tileN * 128 + ldRow) * KD;

    float acc[4][4][4];
    #pragma unroll
    for (int i = 0; i < 4; ++i)
        #pragma unroll
        for (int j = 0; j < 4; ++j)
            #pragma unroll
            for (int q = 0; q < 4; ++q) acc[i][j][q] = 0.f;

    auto load_stage = [&](int it) {
        const int k0 = it * 64;
        const uint32_t base  = sb + (it & 1) * STAGE2;
        const uint32_t swrow = (uint32_t)(ldRow & 7);
        #pragma unroll
        for (int c = 0; c < 4; ++c) {
            uint32_t ch = (uint32_t)(ldC0 + c);
            uint32_t sw = (ch ^ swrow) * 16u + (uint32_t)ldRow * 128u;
            cp_async16(base + sw,          A  + arow + k0 + ch * 8);
            cp_async16(base + 16384 + sw,  B0 + brow + k0 + ch * 8);
            cp_async16(base + 32768 + sw,  B1 + brow + k0 + ch * 8);
        }
        cp_commit();
    };

    uint32_t a[4][4], b[2][4][2];

    auto load_a = [&](uint32_t ab, int ks) {
        #pragma unroll
        for (int mt = 0; mt < 4; ++mt) {
            int row = wm * 64 + mt * 16 + lrow;
            uint32_t ch = (uint32_t)(ks * 2 + lsel);
            uint32_t ad = ab + (uint32_t)row * 128u + ((ch ^ (uint32_t)(row & 7)) * 16u);
            ldsm_x4(a[mt][0], a[mt][1], a[mt][2], a[mt][3], ad);
        }
    };
    auto load_b = [&](uint32_t bb, int ks, int half) {
        #pragma unroll
        for (int nt2 = 0; nt2 < 2; ++nt2) {
            int row = wn * 32 + nt2 * 16 + lrow;
            uint32_t ch = (uint32_t)(ks * 2 + lsel);
            uint32_t bd = bb + (uint32_t)row * 128u + ((ch ^ (uint32_t)(row & 7)) * 16u);
            uint32_t r0, r1, r2, r3;
            ldsm_x4(r0, r1, r2, r3, bd);
            b[half][nt2 * 2 + 0][0] = r0; b[half][nt2 * 2 + 1][0] = r1;
            b[half][nt2 * 2 + 0][1] = r2; b[half][nt2 * 2 + 1][1] = r3;
        }
    };

    load_stage(0);

    for (int it = 0; it < 8; ++it) {
        if (it < 7) load_stage(it + 1);
        else cp_commit();
        cp_wait<1>();
        __syncthreads();

        const uint32_t base = sb + (it & 1) * STAGE2;

        #pragma unroll
        for (int ks = 0; ks < 4; ++ks) {
            load_a(base, ks);
            load_b(base + 16384, ks, 0);
            load_b(base + 32768, ks, 1);
            #pragma unroll
            for (int h2 = 0; h2 < 2; ++h2)
                #pragma unroll
                for (int mt = 0; mt < 4; ++mt)
                    #pragma unroll
                    for (int nt = 0; nt < 4; ++nt)
                        mma16816(acc[mt][nt][0], acc[mt][nt][1],
                                 acc[mt][nt][2], acc[mt][nt][3],
                                 a[mt][0], a[mt][1], a[mt][2], a[mt][3],
                                 b[h2][nt][0], b[h2][nt][1]);
        }
        __syncthreads();
    }
    cp_wait<0>();

    const int rbase = tileM * 128 + wm * 64 + (lane >> 2);
    const int cbase = tileN * 128 + wn * 32 + (lane & 3) * 2;
    #pragma unroll
    for (int mt = 0; mt < 4; ++mt) {
        #pragma unroll
        for (int nt = 0; nt < 4; ++nt) {
            int r0 = rbase + mt * 16;
            int cc = cbase + nt * 8;
            *reinterpret_cast<float2*>(C + (size_t)r0 * ND + cc) =
                make_float2(acc[mt][nt][0], acc[mt][nt][1]);
            *reinterpret_cast<float2*>(C + (size_t)(r0 + 8) * ND + cc) =
                make_float2(acc[mt][nt][2], acc[mt][nt][3]);
        }
    }
}

// ---------------- fp32 -> bf16 2-split (x and weights) ---------------------
__global__ void __launch_bounds__(256) split2_kernel(
    const float4* __restrict__ in, uint2* __restrict__ o0,
    uint2* __restrict__ o1, int n4)
{
    if (blockIdx.x == 0 && threadIdx.x == 0) g_flag_count = 0;
    int i = blockIdx.x * blockDim.x + threadIdx.x;
    if (i >= n4) return;
    float4 v = in[i];
    float f[4] = {v.x, v.y, v.z, v.w};
    unsigned short a[4], b[4];
    #pragma unroll
    for (int j = 0; j < 4; ++j) {
        __nv_bfloat16 h0 = __float2bfloat16_rn(f[j]);
        float r = f[j] - __bfloat162float(h0);
        __nv_bfloat16 h1 = __float2bfloat16_rn(r);
        a[j] = __bfloat16_as_ushort(h0);
        b[j] = __bfloat16_as_ushort(h1);
    }
    o0[i] = make_uint2((uint32_t)a[0] | ((uint32_t)a[1] << 16),
                       (uint32_t)a[2] | ((uint32_t)a[3] << 16));
    o1[i] = make_uint2((uint32_t)b[0] | ((uint32_t)b[1] << 16),
                       (uint32_t)b[2] | ((uint32_t)b[3] << 16));
}

// ---------------- exact fix-up: bit-identical sequential fp32 dot ----------
__global__ void __launch_bounds__(128) fixup_kernel(
    const float* __restrict__ x, const float* __restrict__ W1,
    __nv_bfloat16* __restrict__ s)
{
    int count = g_flag_count;
    if (count > FLAG_CAP) count = FLAG_CAP;
    for (int j = blockIdx.x * blockDim.x + threadIdx.x; j < count;
         j += gridDim.x * blockDim.x) {
        const int idx = g_flags[j];
        const int bn  = idx >> 9;
        const int c   = idx & 511;
        const float4* w = reinterpret_cast<const float4*>(W1 + (size_t)c * KD);
        float v = 0.0f;
        #pragma unroll 1
        for (int t = 0; t < 4; ++t) {
            const float4* xr = reinterpret_cast<const float4*>(
                x + ((size_t)t * MPERT + bn) * KD);
            float acc = 0.0f;
            // single accumulator, ascending k: bit-identical to reference
            for (int k4 = 0; k4 < KD / 4; ++k4) {
                float4 xv = xr[k4];
                float4 wv = w[k4];
                acc = fmaf(xv.x, wv.x, acc);
                acc = fmaf(xv.y, wv.y, acc);
                acc = fmaf(xv.z, wv.z, acc);
                acc = fmaf(xv.w, wv.w, acc);
            }
            v = v + (acc - v) / 2.0f;
            bool fire = (v >= 1.0f);
            s[(size_t)t * NCHAN + idx] =
                __ushort_as_bfloat16(fire ? (unsigned short)0x3F80 : (unsigned short)0);
            if (fire) v = 0.0f;
        }
    }
}

// ---------------- launch ----------------
extern "C" void kernel_launch(void* const* d_in, const int* in_sizes, int n_in,
                              void* d_out, int out_size)
{
    const float* x  = (const float*)d_in[0];
    const float* W1 = (const float*)d_in[1];
    const float* W2 = (const float*)d_in[2];
    float* out = (float*)d_out;

    __nv_bfloat16 *x0, *x1, *w10, *w11, *w20, *w21, *s;
    cudaGetSymbolAddress((void**)&x0,  g_x0);
    cudaGetSymbolAddress((void**)&x1,  g_x1);
    cudaGetSymbolAddress((void**)&w10, g_w10);
    cudaGetSymbolAddress((void**)&w11, g_w11);
    cudaGetSymbolAddress((void**)&w20, g_w20);
    cudaGetSymbolAddress((void**)&w21, g_w21);
    cudaGetSymbolAddress((void**)&s,   g_s);

    cudaFuncSetAttribute(gemm1_fused,
                         cudaFuncAttributeMaxDynamicSharedMemorySize, SMEM1);
    cudaFuncSetAttribute(gemm2_kernel,
                         cudaFuncAttributeMaxDynamicSharedMemorySize, SMEM2);

    // splits (x split also zeroes the flag counter)
    split2_kernel<<<(MTOT * KD / 4) / 256, 256>>>(
        (const float4*)x, (uint2*)x0, (uint2*)x1, MTOT * KD / 4);
    split2_kernel<<<(KD * ND / 4) / 256, 256>>>(
        (const float4*)W1, (uint2*)w10, (uint2*)w11, KD * ND / 4);
    split2_kernel<<<(KD * ND / 4) / 256, 256>>>(
        (const float4*)W2, (uint2*)w20, (uint2*)w21, KD * ND / 4);

    // GEMM1 fused: h = x0@w10 + x0@w11 + x1@w10; LIF + flags in epilogue
    gemm1_fused<<<dim3(4, 256), 512, SMEM1>>>(x0, x1, w10, w11, s);

    // exact fix-up of near-threshold channels (bit-identical to reference)
    fixup_kernel<<<256, 128>>>(x, W1, s);

    // GEMM2: out = s@w20 + s@w21 (spikes exact in bf16)
    gemm2_kernel<<<dim3(4, 256), 256, SMEM2>>>(s, w20, w21, out);
}

// round 8
// speedup vs baseline: 1.4594x; 1.1078x over previous
#include <cuda_runtime.h>
#include <cuda_bf16.h>
#include <cuda_fp16.h>
#include <cstdint>

// Shapes (fixed): x [4,8,1024,512] -> M=32768 rows, K=512; W1,W2 [512,512].
#define MTOT  32768
#define MPERT 8192
#define KD    512
#define ND    512
#define NCHAN (MPERT * ND)
#define FLAG_CAP 262144
#define MARGIN 1e-4f

// ---------------- scratch (no cudaMalloc allowed) ----------------
__device__ __align__(16) __nv_bfloat16 g_x0[(size_t)MTOT * KD];
__device__ __align__(16) __nv_bfloat16 g_x1[(size_t)MTOT * KD];
__device__ __align__(16) __nv_bfloat16 g_w10[KD * ND];
__device__ __align__(16) __nv_bfloat16 g_w11[KD * ND];
__device__ __align__(16) unsigned short g_w2h[KD * ND];      // W2 in fp16
__device__ __align__(16) unsigned short g_s[(size_t)MTOT * ND]; // spikes fp16
__device__ int g_flags[FLAG_CAP];
__device__ int g_flag_count;

// ---------------- base-target PTX helpers (sm_80-era only) -----------------
__device__ __forceinline__ uint32_t smem_u32(const void* p) {
    uint32_t a;
    asm("{ .reg .u64 t; cvta.to.shared.u64 t, %1; cvt.u32.u64 %0, t; }"
        : "=r"(a) : "l"(p));
    return a;
}
__device__ __forceinline__ void cp_async16(uint32_t dst, const void* src) {
    asm volatile("cp.async.cg.shared.global [%0], [%1], 16;"
                 :: "r"(dst), "l"(src) : "memory");
}
__device__ __forceinline__ void cp_commit() {
    asm volatile("cp.async.commit_group;" ::: "memory");
}
template <int N>
__device__ __forceinline__ void cp_wait() {
    asm volatile("cp.async.wait_group %0;" :: "n"(N) : "memory");
}
__device__ __forceinline__ void ldsm_x4(uint32_t& r0, uint32_t& r1,
                                        uint32_t& r2, uint32_t& r3, uint32_t a) {
    asm volatile("ldmatrix.sync.aligned.m8n8.x4.shared.b16 {%0,%1,%2,%3}, [%4];"
                 : "=r"(r0), "=r"(r1), "=r"(r2), "=r"(r3) : "r"(a));
}
__device__ __forceinline__ void mma_bf16(float& c0, float& c1, float& c2, float& c3,
                                         uint32_t a0, uint32_t a1, uint32_t a2, uint32_t a3,
                                         uint32_t b0, uint32_t b1) {
    asm volatile(
        "mma.sync.aligned.m16n8k16.row.col.f32.bf16.bf16.f32 "
        "{%0,%1,%2,%3}, {%4,%5,%6,%7}, {%8,%9}, {%0,%1,%2,%3};"
        : "+f"(c0), "+f"(c1), "+f"(c2), "+f"(c3)
        : "r"(a0), "r"(a1), "r"(a2), "r"(a3), "r"(b0), "r"(b1));
}
__device__ __forceinline__ void mma_fp16(float& c0, float& c1, float& c2, float& c3,
                                         uint32_t a0, uint32_t a1, uint32_t a2, uint32_t a3,
                                         uint32_t b0, uint32_t b1) {
    asm volatile(
        "mma.sync.aligned.m16n8k16.row.col.f32.f16.f16.f32 "
        "{%0,%1,%2,%3}, {%4,%5,%6,%7}, {%8,%9}, {%0,%1,%2,%3};"
        : "+f"(c0), "+f"(c1), "+f"(c2), "+f"(c3)
        : "r"(a0), "r"(a1), "r"(a2), "r"(a3), "r"(b0), "r"(b1));
}

// ============================================================================
// GEMM1 (fused): h = A0@B0^T + A0@B1^T + A1@B0^T, LIF + flags in epilogue.
// 512 threads (16 warps, 4x4), CTA tile 128x128, BK=64, 64KB stage x3.
// M rows t-interleaved: smem row r <-> (t=(r>>3)&3, bn=tileM*32+(r&7)+8*(r>>5)).
// Spikes written as fp16 (1.0 = 0x3C00).
// ============================================================================
#define SMEM1 196608

__global__ void __launch_bounds__(512, 1) gemm1_fused(
    const __nv_bfloat16* __restrict__ A0, const __nv_bfloat16* __restrict__ A1,
    const __nv_bfloat16* __restrict__ B0, const __nv_bfloat16* __restrict__ B1,
    unsigned short* __restrict__ s)
{
    extern __shared__ char dynsmem[];
    const uint32_t sb = smem_u32(dynsmem);

    const int tid  = threadIdx.x;
    const int lane = tid & 31;
    const int warp = tid >> 5;
    const int wm   = warp >> 2;
    const int wn   = warp & 3;
    const int tileN = blockIdx.x;
    const int tileM = blockIdx.y;

    const int ldRow = tid >> 2;
    const int ldC0  = (tid & 3) * 2;
    const int lrow  = lane & 15;
    const int lsel  = lane >> 4;

    const int t_   = (ldRow >> 3) & 3;
    const int bno  = (ldRow & 7) | ((ldRow >> 5) << 3);
    const size_t arow = ((size_t)t_ * MPERT + tileM * 32 + bno) * KD;
    const size_t brow = ((size_t)tileN * 128 + ldRow) * KD;

    float acc[2][4][4];
    #pragma unroll
    for (int i = 0; i < 2; ++i)
        #pragma unroll
        for (int j = 0; j < 4; ++j)
            #pragma unroll
            for (int q = 0; q < 4; ++q) acc[i][j][q] = 0.f;

    auto load_stage = [&](int it) {
        const int k0 = it * 64;
        const uint32_t base = sb + (uint32_t)(it % 3) * 65536u;
        const uint32_t swr  = (uint32_t)(ldRow & 7);
        #pragma unroll
        for (int c = 0; c < 2; ++c) {
            uint32_t ch = (uint32_t)(ldC0 + c);
            uint32_t sw = (ch ^ swr) * 16u + (uint32_t)ldRow * 128u;
            cp_async16(base + sw,          A0 + arow + k0 + ch * 8);
            cp_async16(base + 16384 + sw,  A1 + arow + k0 + ch * 8);
            cp_async16(base + 32768 + sw,  B0 + brow + k0 + ch * 8);
            cp_async16(base + 49152 + sw,  B1 + brow + k0 + ch * 8);
        }
        cp_commit();
    };

    load_stage(0);
    load_stage(1);

    uint32_t a0f[2][4], a1f[2][4], b0f[4][2], b1f[4][2];

    auto load_afrag = [&](uint32_t tb, int ks, uint32_t (&f)[2][4]) {
        #pragma unroll
        for (int mt = 0; mt < 2; ++mt) {
            int row = wm * 32 + mt * 16 + lrow;
            uint32_t ch = (uint32_t)(ks * 2 + lsel);
            uint32_t ad = tb + (uint32_t)row * 128u + ((ch ^ (uint32_t)(row & 7)) * 16u);
            ldsm_x4(f[mt][0], f[mt][1], f[mt][2], f[mt][3], ad);
        }
    };
    auto load_bfrag = [&](uint32_t tb, int ks, uint32_t (&f)[4][2]) {
        #pragma unroll
        for (int nt2 = 0; nt2 < 2; ++nt2) {
            int row = wn * 32 + nt2 * 16 + lrow;
            uint32_t ch = (uint32_t)(ks * 2 + lsel);
            uint32_t bd = tb + (uint32_t)row * 128u + ((ch ^ (uint32_t)(row & 7)) * 16u);
            uint32_t r0, r1, r2, r3;
            ldsm_x4(r0, r1, r2, r3, bd);
            f[nt2 * 2 + 0][0] = r0; f[nt2 * 2 + 1][0] = r1;
            f[nt2 * 2 + 0][1] = r2; f[nt2 * 2 + 1][1] = r3;
        }
    };

    for (int it = 0; it < 8; ++it) {
        if (it + 2 < 8) load_stage(it + 2);
        else cp_commit();
        cp_wait<2>();
        __syncthreads();

        const uint32_t base = sb + (uint32_t)(it % 3) * 65536u;

        #pragma unroll
        for (int ks = 0; ks < 4; ++ks) {
            load_afrag(base,          ks, a0f);
            load_afrag(base + 16384,  ks, a1f);
            load_bfrag(base + 32768,  ks, b0f);
            load_bfrag(base + 49152,  ks, b1f);
            #pragma unroll
            for (int mt = 0; mt < 2; ++mt)
                #pragma unroll
                for (int nt = 0; nt < 4; ++nt)
                    mma_bf16(acc[mt][nt][0], acc[mt][nt][1],
                             acc[mt][nt][2], acc[mt][nt][3],
                             a0f[mt][0], a0f[mt][1], a0f[mt][2], a0f[mt][3],
                             b0f[nt][0], b0f[nt][1]);
            #pragma unroll
            for (int mt = 0; mt < 2; ++mt)
                #pragma unroll
                for (int nt = 0; nt < 4; ++nt)
                    mma_bf16(acc[mt][nt][0], acc[mt][nt][1],
                             acc[mt][nt][2], acc[mt][nt][3],
                             a0f[mt][0], a0f[mt][1], a0f[mt][2], a0f[mt][3],
                             b1f[nt][0], b1f[nt][1]);
            #pragma unroll
            for (int mt = 0; mt < 2; ++mt)
                #pragma unroll
                for (int nt = 0; nt < 4; ++nt)
                    mma_bf16(acc[mt][nt][0], acc[mt][nt][1],
                             acc[mt][nt][2], acc[mt][nt][3],
                             a1f[mt][0], a1f[mt][1], a1f[mt][2], a1f[mt][3],
                             b0f[nt][0], b0f[nt][1]);
        }
        __syncthreads();
    }
    cp_wait<0>();

    // LIF epilogue: row r = wm*32 + mt*16 + k*8 + (lane>>2) -> t=2mt+k,
    // bn = tileM*32 + (lane>>2) + 8*wm. Spike 1.0 in fp16 = 0x3C00.
    {
        const int bn = tileM * 32 + (lane >> 2) + 8 * wm;
        const int c0base = tileN * 128 + wn * 32 + (lane & 3) * 2;
        #pragma unroll
        for (int nt = 0; nt < 4; ++nt) {
            const int c0 = c0base + nt * 8;
            float v0 = 0.f, v1 = 0.f;
            bool r0 = false, r1 = false;
            uint32_t pk[4];
            #pragma unroll
            for (int t = 0; t < 4; ++t) {
                const int mt = t >> 1;
                const int q  = (t & 1) * 2;
                float h0 = acc[mt][nt][q + 0];
                float h1 = acc[mt][nt][q + 1];
                v0 = v0 + (h0 - v0) / 2.0f;
                v1 = v1 + (h1 - v1) / 2.0f;
                r0 |= (fabsf(v0 - 1.0f) < MARGIN);
                r1 |= (fabsf(v1 - 1.0f) < MARGIN);
                bool f0 = (v0 >= 1.0f), f1 = (v1 >= 1.0f);
                pk[t] = (f0 ? 0x3C00u : 0u) | ((f1 ? 0x3C00u : 0u) << 16);
                if (f0) v0 = 0.f;
                if (f1) v1 = 0.f;
            }
            #pragma unroll
            for (int t = 0; t < 4; ++t)
                *reinterpret_cast<uint32_t*>(
                    s + ((size_t)t * MPERT + bn) * ND + c0) = pk[t];
            if (r0) {
                int slot = atomicAdd(&g_flag_count, 1);
                if (slot < FLAG_CAP) g_flags[slot] = bn * ND + c0;
            }
            if (r1) {
                int slot = atomicAdd(&g_flag_count, 1);
                if (slot < FLAG_CAP) g_flags[slot] = bn * ND + c0 + 1;
            }
        }
    }
}

// ============================================================================
// GEMM2: out = s @ W2h^T, single fp16 product.
// 256 threads (8 warps @ 64x32), CTA 128x128, stage 32KB x 3 (2 CTA/SM).
// ============================================================================
#define STAGE2 32768
#define SMEM2  98304

__global__ void __launch_bounds__(256, 2) gemm2_kernel(
    const unsigned short* __restrict__ A, const unsigned short* __restrict__ B,
    float* __restrict__ C)
{
    extern __shared__ char dynsmem[];
    const uint32_t sb = smem_u32(dynsmem);

    const int tid   = threadIdx.x;
    const int lane  = tid & 31;
    const int warp  = tid >> 5;
    const int wm    = warp >> 2;
    const int wn    = warp & 3;
    const int tileN = blockIdx.x;
    const int tileM = blockIdx.y;

    const int ldRow = tid >> 1;
    const int ldC0  = (tid & 1) * 4;
    const int lrow  = lane & 15;
    const int lsel  = lane >> 4;

    const size_t arow = ((size_t)tileM * 128 + ldRow) * KD;
    const size_t brow = ((size_t)tileN * 128 + ldRow) * KD;

    float acc[4][4][4];
    #pragma unroll
    for (int i = 0; i < 4; ++i)
        #pragma unroll
        for (int j = 0; j < 4; ++j)
            #pragma unroll
            for (int q = 0; q < 4; ++q) acc[i][j][q] = 0.f;

    auto load_stage = [&](int it) {
        const int k0 = it * 64;
        const uint32_t base  = sb + (uint32_t)(it % 3) * STAGE2;
        const uint32_t swrow = (uint32_t)(ldRow & 7);
        #pragma unroll
        for (int c = 0; c < 4; ++c) {
            uint32_t ch = (uint32_t)(ldC0 + c);
            uint32_t sw = (ch ^ swrow) * 16u + (uint32_t)ldRow * 128u;
            cp_async16(base + sw,          A + arow + k0 + ch * 8);
            cp_async16(base + 16384 + sw,  B + brow + k0 + ch * 8);
        }
        cp_commit();
    };

    uint32_t a[4][4], b[4][2];

    auto load_a = [&](uint32_t ab, int ks) {
        #pragma unroll
        for (int mt = 0; mt < 4; ++mt) {
            int row = wm * 64 + mt * 16 + lrow;
            uint32_t ch = (uint32_t)(ks * 2 + lsel);
            uint32_t ad = ab + (uint32_t)row * 128u + ((ch ^ (uint32_t)(row & 7)) * 16u);
            ldsm_x4(a[mt][0], a[mt][1], a[mt][2], a[mt][3], ad);
        }
    };
    auto load_b = [&](uint32_t bb, int ks) {
        #pragma unroll
        for (int nt2 = 0; nt2 < 2; ++nt2) {
            int row = wn * 32 + nt2 * 16 + lrow;
            uint32_t ch = (uint32_t)(ks * 2 + lsel);
            uint32_t bd = bb + (uint32_t)row * 128u + ((ch ^ (uint32_t)(row & 7)) * 16u);
            uint32_t r0, r1, r2, r3;
            ldsm_x4(r0, r1, r2, r3, bd);
            b[nt2 * 2 + 0][0] = r0; b[nt2 * 2 + 1][0] = r1;
            b[nt2 * 2 + 0][1] = r2; b[nt2 * 2 + 1][1] = r3;
        }
    };

    load_stage(0);
    load_stage(1);

    for (int it = 0; it < 8; ++it) {
        if (it + 2 < 8) load_stage(it + 2);
        else cp_commit();
        cp_wait<2>();
        __syncthreads();

        const uint32_t base = sb + (uint32_t)(it % 3) * STAGE2;

        #pragma unroll
        for (int ks = 0; ks < 4; ++ks) {
            load_a(base, ks);
            load_b(base + 16384, ks);
            #pragma unroll
            for (int mt = 0; mt < 4; ++mt)
                #pragma unroll
                for (int nt = 0; nt < 4; ++nt)
                    mma_fp16(acc[mt][nt][0], acc[mt][nt][1],
                             acc[mt][nt][2], acc[mt][nt][3],
                             a[mt][0], a[mt][1], a[mt][2], a[mt][3],
                             b[nt][0], b[nt][1]);
        }
        __syncthreads();
    }
    cp_wait<0>();

    const int rbase = tileM * 128 + wm * 64 + (lane >> 2);
    const int cbase = tileN * 128 + wn * 32 + (lane & 3) * 2;
    #pragma unroll
    for (int mt = 0; mt < 4; ++mt) {
        #pragma unroll
        for (int nt = 0; nt < 4; ++nt) {
            int r0 = rbase + mt * 16;
            int cc = cbase + nt * 8;
            *reinterpret_cast<float2*>(C + (size_t)r0 * ND + cc) =
                make_float2(acc[mt][nt][0], acc[mt][nt][1]);
            *reinterpret_cast<float2*>(C + (size_t)(r0 + 8) * ND + cc) =
                make_float2(acc[mt][nt][2], acc[mt][nt][3]);
        }
    }
}

// ---------------- fp32 -> bf16 2-split (x, W1) ----------------
__global__ void __launch_bounds__(256) split2_kernel(
    const float4* __restrict__ in, uint2* __restrict__ o0,
    uint2* __restrict__ o1, int n4)
{
    if (blockIdx.x == 0 && threadIdx.x == 0) g_flag_count = 0;
    int i = blockIdx.x * blockDim.x + threadIdx.x;
    if (i >= n4) return;
    float4 v = in[i];
    float f[4] = {v.x, v.y, v.z, v.w};
    unsigned short a[4], b[4];
    #pragma unroll
    for (int j = 0; j < 4; ++j) {
        __nv_bfloat16 h0 = __float2bfloat16_rn(f[j]);
        float r = f[j] - __bfloat162float(h0);
        __nv_bfloat16 h1 = __float2bfloat16_rn(r);
        a[j] = __bfloat16_as_ushort(h0);
        b[j] = __bfloat16_as_ushort(h1);
    }
    o0[i] = make_uint2((uint32_t)a[0] | ((uint32_t)a[1] << 16),
                       (uint32_t)a[2] | ((uint32_t)a[3] << 16));
    o1[i] = make_uint2((uint32_t)b[0] | ((uint32_t)b[1] << 16),
                       (uint32_t)b[2] | ((uint32_t)b[3] << 16));
}

// ---------------- fp32 -> fp16 convert (W2) ----------------
__global__ void __launch_bounds__(256) conv_fp16_kernel(
    const float4* __restrict__ in, uint2* __restrict__ o, int n4)
{
    int i = blockIdx.x * blockDim.x + threadIdx.x;
    if (i >= n4) return;
    float4 v = in[i];
    __half2 lo = __floats2half2_rn(v.x, v.y);
    __half2 hi = __floats2half2_rn(v.z, v.w);
    o[i] = make_uint2(*reinterpret_cast<uint32_t*>(&lo),
                      *reinterpret_cast<uint32_t*>(&hi));
}

// ---------------- exact fix-up: bit-identical sequential fp32 dot ----------
__global__ void __launch_bounds__(128) fixup_kernel(
    const float* __restrict__ x, const float* __restrict__ W1,
    unsigned short* __restrict__ s)
{
    int count = g_flag_count;
    if (count > FLAG_CAP) count = FLAG_CAP;
    for (int j = blockIdx.x * blockDim.x + threadIdx.x; j < count;
         j += gridDim.x * blockDim.x) {
        const int idx = g_flags[j];
        const int bn  = idx >> 9;
        const int c   = idx & 511;
        const float4* w = reinterpret_cast<const float4*>(W1 + (size_t)c * KD);
        float v = 0.0f;
        #pragma unroll 1
        for (int t = 0; t < 4; ++t) {
            const float4* xr = reinterpret_cast<const float4*>(
                x + ((size_t)t * MPERT + bn) * KD);
            float acc = 0.0f;
            for (int k4 = 0; k4 < KD / 4; ++k4) {
                float4 xv = xr[k4];
                float4 wv = w[k4];
                acc = fmaf(xv.x, wv.x, acc);
                acc = fmaf(xv.y, wv.y, acc);
                acc = fmaf(xv.z, wv.z, acc);
                acc = fmaf(xv.w, wv.w, acc);
            }
            v = v + (acc - v) / 2.0f;
            bool fire = (v >= 1.0f);
            s[(size_t)t * NCHAN + idx] = fire ? (unsigned short)0x3C00 : (unsigned short)0;
            if (fire) v = 0.0f;
        }
    }
}

// ---------------- launch ----------------
extern "C" void kernel_launch(void* const* d_in, const int* in_sizes, int n_in,
                              void* d_out, int out_size)
{
    const float* x  = (const float*)d_in[0];
    const float* W1 = (const float*)d_in[1];
    const float* W2 = (const float*)d_in[2];
    float* out = (float*)d_out;

    __nv_bfloat16 *x0, *x1, *w10, *w11;
    unsigned short *w2h, *s;
    cudaGetSymbolAddress((void**)&x0,  g_x0);
    cudaGetSymbolAddress((void**)&x1,  g_x1);
    cudaGetSymbolAddress((void**)&w10, g_w10);
    cudaGetSymbolAddress((void**)&w11, g_w11);
    cudaGetSymbolAddress((void**)&w2h, g_w2h);
    cudaGetSymbolAddress((void**)&s,   g_s);

    cudaFuncSetAttribute(gemm1_fused,
                         cudaFuncAttributeMaxDynamicSharedMemorySize, SMEM1);
    cudaFuncSetAttribute(gemm2_kernel,
                         cudaFuncAttributeMaxDynamicSharedMemorySize, SMEM2);

    split2_kernel<<<(MTOT * KD / 4) / 256, 256>>>(
        (const float4*)x, (uint2*)x0, (uint2*)x1, MTOT * KD / 4);
    split2_kernel<<<(KD * ND / 4) / 256, 256>>>(
        (const float4*)W1, (uint2*)w10, (uint2*)w11, KD * ND / 4);
    conv_fp16_kernel<<<(KD * ND / 4) / 256, 256>>>(
        (const float4*)W2, (uint2*)w2h, KD * ND / 4);

    // GEMM1 fused: h = x0@w10 + x0@w11 + x1@w10; LIF + flags in epilogue
    gemm1_fused<<<dim3(4, 256), 512, SMEM1>>>(x0, x1, w10, w11, s);

    // exact fix-up of near-threshold channels (bit-identical to reference)
    fixup_kernel<<<256, 128>>>(x, W1, s);

    // GEMM2: out = s @ W2h^T, single fp16 product
    gemm2_kernel<<<dim3(4, 256), 256, SMEM2>>>(s, w2h, out);
}

// round 9
// speedup vs baseline: 2.4849x; 1.7026x over previous
#include <cuda_runtime.h>
#include <cuda_bf16.h>
#include <cuda_fp16.h>
#include <cstdint>

// Shapes (fixed): x [4,8,1024,512] -> M=32768 rows, K=512; W1,W2 [512,512].
#define MTOT  32768
#define MPERT 8192
#define KD    512
#define ND    512
#define NCHAN (MPERT * ND)
#define FLAG_CAP 1048576
#define MARGIN 4e-3f

// ---------------- scratch (no cudaMalloc allowed) ----------------
__device__ __align__(16) unsigned short g_xh[(size_t)MTOT * KD];   // x fp16
__device__ __align__(16) unsigned short g_w1h[KD * ND];            // W1 fp16
__device__ __align__(16) unsigned short g_w2h[KD * ND];            // W2 fp16
__device__ __align__(16) unsigned short g_s[(size_t)MTOT * ND];    // spikes fp16
__device__ int g_flags[FLAG_CAP];
__device__ int g_flag_count;

// ---------------- base-target PTX helpers (sm_80-era only) -----------------
__device__ __forceinline__ uint32_t smem_u32(const void* p) {
    uint32_t a;
    asm("{ .reg .u64 t; cvta.to.shared.u64 t, %1; cvt.u32.u64 %0, t; }"
        : "=r"(a) : "l"(p));
    return a;
}
__device__ __forceinline__ void cp_async16(uint32_t dst, const void* src) {
    asm volatile("cp.async.cg.shared.global [%0], [%1], 16;"
                 :: "r"(dst), "l"(src) : "memory");
}
__device__ __forceinline__ void cp_commit() {
    asm volatile("cp.async.commit_group;" ::: "memory");
}
template <int N>
__device__ __forceinline__ void cp_wait() {
    asm volatile("cp.async.wait_group %0;" :: "n"(N) : "memory");
}
__device__ __forceinline__ void ldsm_x4(uint32_t& r0, uint32_t& r1,
                                        uint32_t& r2, uint32_t& r3, uint32_t a) {
    asm volatile("ldmatrix.sync.aligned.m8n8.x4.shared.b16 {%0,%1,%2,%3}, [%4];"
                 : "=r"(r0), "=r"(r1), "=r"(r2), "=r"(r3) : "r"(a));
}
__device__ __forceinline__ void mma_fp16(float& c0, float& c1, float& c2, float& c3,
                                         uint32_t a0, uint32_t a1, uint32_t a2, uint32_t a3,
                                         uint32_t b0, uint32_t b1) {
    asm volatile(
        "mma.sync.aligned.m16n8k16.row.col.f32.f16.f16.f32 "
        "{%0,%1,%2,%3}, {%4,%5,%6,%7}, {%8,%9}, {%0,%1,%2,%3};"
        : "+f"(c0), "+f"(c1), "+f"(c2), "+f"(c3)
        : "r"(a0), "r"(a1), "r"(a2), "r"(a3), "r"(b0), "r"(b1));
}

// ============================================================================
// GEMM1 (fused): h = x_h @ W1_h^T (single fp16 product), LIF + flags epilogue.
// 256 threads (8 warps @ 64x32), CTA 128x128, BK=64, 32KB stage x3 (2 CTA/SM).
// M rows t-interleaved: smem row r <-> (t=(r>>3)&3, bn=tileM*32+(r&7)+8*(r>>5))
// Epilogue (round-6 verified): frag row r = wm*64+mt*16+k*8+l4 ->
//   t=(2mt+k)&3, bn=tileM*32+l4+8*(2wm+(mt>>1)); h_t = acc[2g+(t>>1)][nt][(t&1)*2+cc]
// ============================================================================
#define STAGE1 32768
#define SMEM1  98304

__global__ void __launch_bounds__(256, 2) gemm1_fused(
    const unsigned short* __restrict__ A, const unsigned short* __restrict__ B,
    unsigned short* __restrict__ s)
{
    extern __shared__ char dynsmem[];
    const uint32_t sb = smem_u32(dynsmem);

    const int tid   = threadIdx.x;
    const int lane  = tid & 31;
    const int warp  = tid >> 5;
    const int wm    = warp >> 2;
    const int wn    = warp & 3;
    const int tileN = blockIdx.x;
    const int tileM = blockIdx.y;

    const int ldRow = tid >> 1;
    const int ldC0  = (tid & 1) * 4;
    const int lrow  = lane & 15;
    const int lsel  = lane >> 4;

    // t-interleaved A row
    const int t_  = (ldRow >> 3) & 3;
    const int bno = (ldRow & 7) | ((ldRow >> 5) << 3);
    const size_t arow = ((size_t)t_ * MPERT + tileM * 32 + bno) * KD;
    const size_t brow = ((size_t)tileN * 128 + ldRow) * KD;

    float acc[4][4][4];
    #pragma unroll
    for (int i = 0; i < 4; ++i)
        #pragma unroll
        for (int j = 0; j < 4; ++j)
            #pragma unroll
            for (int q = 0; q < 4; ++q) acc[i][j][q] = 0.f;

    auto load_stage = [&](int it) {
        const int k0 = it * 64;
        const uint32_t base  = sb + (uint32_t)(it % 3) * STAGE1;
        const uint32_t swrow = (uint32_t)(ldRow & 7);
        #pragma unroll
        for (int c = 0; c < 4; ++c) {
            uint32_t ch = (uint32_t)(ldC0 + c);
            uint32_t sw = (ch ^ swrow) * 16u + (uint32_t)ldRow * 128u;
            cp_async16(base + sw,          A + arow + k0 + ch * 8);
            cp_async16(base + 16384 + sw,  B + brow + k0 + ch * 8);
        }
        cp_commit();
    };

    uint32_t a[4][4], b[4][2];

    auto load_a = [&](uint32_t ab, int ks) {
        #pragma unroll
        for (int mt = 0; mt < 4; ++mt) {
            int row = wm * 64 + mt * 16 + lrow;
            uint32_t ch = (uint32_t)(ks * 2 + lsel);
            uint32_t ad = ab + (uint32_t)row * 128u + ((ch ^ (uint32_t)(row & 7)) * 16u);
            ldsm_x4(a[mt][0], a[mt][1], a[mt][2], a[mt][3], ad);
        }
    };
    auto load_b = [&](uint32_t bb, int ks) {
        #pragma unroll
        for (int nt2 = 0; nt2 < 2; ++nt2) {
            int row = wn * 32 + nt2 * 16 + lrow;
            uint32_t ch = (uint32_t)(ks * 2 + lsel);
            uint32_t bd = bb + (uint32_t)row * 128u + ((ch ^ (uint32_t)(row & 7)) * 16u);
            uint32_t r0, r1, r2, r3;
            ldsm_x4(r0, r1, r2, r3, bd);
            b[nt2 * 2 + 0][0] = r0; b[nt2 * 2 + 1][0] = r1;
            b[nt2 * 2 + 0][1] = r2; b[nt2 * 2 + 1][1] = r3;
        }
    };

    load_stage(0);
    load_stage(1);

    for (int it = 0; it < 8; ++it) {
        if (it + 2 < 8) load_stage(it + 2);
        else cp_commit();
        cp_wait<2>();
        __syncthreads();

        const uint32_t base = sb + (uint32_t)(it % 3) * STAGE1;

        #pragma unroll
        for (int ks = 0; ks < 4; ++ks) {
            load_a(base, ks);
            load_b(base + 16384, ks);
            #pragma unroll
            for (int mt = 0; mt < 4; ++mt)
                #pragma unroll
                for (int nt = 0; nt < 4; ++nt)
                    mma_fp16(acc[mt][nt][0], acc[mt][nt][1],
                             acc[mt][nt][2], acc[mt][nt][3],
                             a[mt][0], a[mt][1], a[mt][2], a[mt][3],
                             b[nt][0], b[nt][1]);
        }
        __syncthreads();
    }
    cp_wait<0>();

    // LIF epilogue (round-6 verified mapping); fp16 spike = 0x3C00.
    {
        const int l4 = lane >> 2;
        const int c0base = tileN * 128 + wn * 32 + (lane & 3) * 2;
        #pragma unroll
        for (int nt = 0; nt < 4; ++nt) {
            #pragma unroll
            for (int g = 0; g < 2; ++g) {
                const int bn = tileM * 32 + l4 + 8 * (2 * wm + g);
                const int c0 = c0base + nt * 8;
                float v0 = 0.f, v1 = 0.f;
                bool r0 = false, r1 = false;
                uint32_t pk[4];
                #pragma unroll
                for (int t = 0; t < 4; ++t) {
                    const int mt = 2 * g + (t >> 1);
                    const int q  = (t & 1) * 2;
                    float h0 = acc[mt][nt][q + 0];
                    float h1 = acc[mt][nt][q + 1];
                    v0 = v0 + (h0 - v0) / 2.0f;
                    v1 = v1 + (h1 - v1) / 2.0f;
                    r0 |= (fabsf(v0 - 1.0f) < MARGIN);
                    r1 |= (fabsf(v1 - 1.0f) < MARGIN);
                    bool f0 = (v0 >= 1.0f), f1 = (v1 >= 1.0f);
                    pk[t] = (f0 ? 0x3C00u : 0u) | ((f1 ? 0x3C00u : 0u) << 16);
                    if (f0) v0 = 0.f;
                    if (f1) v1 = 0.f;
                }
                #pragma unroll
                for (int t = 0; t < 4; ++t)
                    *reinterpret_cast<uint32_t*>(
                        s + ((size_t)t * MPERT + bn) * ND + c0) = pk[t];
                if (r0) {
                    int slot = atomicAdd(&g_flag_count, 1);
                    if (slot < FLAG_CAP) g_flags[slot] = bn * ND + c0;
                }
                if (r1) {
                    int slot = atomicAdd(&g_flag_count, 1);
                    if (slot < FLAG_CAP) g_flags[slot] = bn * ND + c0 + 1;
                }
            }
        }
    }
}

// ============================================================================
// GEMM2: out = s @ W2h^T, single fp16 product (round-8 kernel, proven).
// ============================================================================
#define STAGE2 32768
#define SMEM2  98304

__global__ void __launch_bounds__(256, 2) gemm2_kernel(
    const unsigned short* __restrict__ A, const unsigned short* __restrict__ B,
    float* __restrict__ C)
{
    extern __shared__ char dynsmem[];
    const uint32_t sb = smem_u32(dynsmem);

    const int tid   = threadIdx.x;
    const int lane  = tid & 31;
    const int warp  = tid >> 5;
    const int wm    = warp >> 2;
    const int wn    = warp & 3;
    const int tileN = blockIdx.x;
    const int tileM = blockIdx.y;

    const int ldRow = tid >> 1;
    const int ldC0  = (tid & 1) * 4;
    const int lrow  = lane & 15;
    const int lsel  = lane >> 4;

    const size_t arow = ((size_t)tileM * 128 + ldRow) * KD;
    const size_t brow = ((size_t)tileN * 128 + ldRow) * KD;

    float acc[4][4][4];
    #pragma unroll
    for (int i = 0; i < 4; ++i)
        #pragma unroll
        for (int j = 0; j < 4; ++j)
            #pragma unroll
            for (int q = 0; q < 4; ++q) acc[i][j][q] = 0.f;

    auto load_stage = [&](int it) {
        const int k0 = it * 64;
        const uint32_t base  = sb + (uint32_t)(it % 3) * STAGE2;
        const uint32_t swrow = (uint32_t)(ldRow & 7);
        #pragma unroll
        for (int c = 0; c < 4; ++c) {
            uint32_t ch = (uint32_t)(ldC0 + c);
            uint32_t sw = (ch ^ swrow) * 16u + (uint32_t)ldRow * 128u;
            cp_async16(base + sw,          A + arow + k0 + ch * 8);
            cp_async16(base + 16384 + sw,  B + brow + k0 + ch * 8);
        }
        cp_commit();
    };

    uint32_t a[4][4], b[4][2];

    auto load_a = [&](uint32_t ab, int ks) {
        #pragma unroll
        for (int mt = 0; mt < 4; ++mt) {
            int row = wm * 64 + mt * 16 + lrow;
            uint32_t ch = (uint32_t)(ks * 2 + lsel);
            uint32_t ad = ab + (uint32_t)row * 128u + ((ch ^ (uint32_t)(row & 7)) * 16u);
            ldsm_x4(a[mt][0], a[mt][1], a[mt][2], a[mt][3], ad);
        }
    };
    auto load_b = [&](uint32_t bb, int ks) {
        #pragma unroll
        for (int nt2 = 0; nt2 < 2; ++nt2) {
            int row = wn * 32 + nt2 * 16 + lrow;
            uint32_t ch = (uint32_t)(ks * 2 + lsel);
            uint32_t bd = bb + (uint32_t)row * 128u + ((ch ^ (uint32_t)(row & 7)) * 16u);
            uint32_t r0, r1, r2, r3;
            ldsm_x4(r0, r1, r2, r3, bd);
            b[nt2 * 2 + 0][0] = r0; b[nt2 * 2 + 1][0] = r1;
            b[nt2 * 2 + 0][1] = r2; b[nt2 * 2 + 1][1] = r3;
        }
    };

    load_stage(0);
    load_stage(1);

    for (int it = 0; it < 8; ++it) {
        if (it + 2 < 8) load_stage(it + 2);
        else cp_commit();
        cp_wait<2>();
        __syncthreads();

        const uint32_t base = sb + (uint32_t)(it % 3) * STAGE2;

        #pragma unroll
        for (int ks = 0; ks < 4; ++ks) {
            load_a(base, ks);
            load_b(base + 16384, ks);
            #pragma unroll
            for (int mt = 0; mt < 4; ++mt)
                #pragma unroll
                for (int nt = 0; nt < 4; ++nt)
                    mma_fp16(acc[mt][nt][0], acc[mt][nt][1],
                             acc[mt][nt][2], acc[mt][nt][3],
                             a[mt][0], a[mt][1], a[mt][2], a[mt][3],
                             b[nt][0], b[nt][1]);
        }
        __syncthreads();
    }
    cp_wait<0>();

    const int rbase = tileM * 128 + wm * 64 + (lane >> 2);
    const int cbase = tileN * 128 + wn * 32 + (lane & 3) * 2;
    #pragma unroll
    for (int mt = 0; mt < 4; ++mt) {
        #pragma unroll
        for (int nt = 0; nt < 4; ++nt) {
            int r0 = rbase + mt * 16;
            int cc = cbase + nt * 8;
            *reinterpret_cast<float2*>(C + (size_t)r0 * ND + cc) =
                make_float2(acc[mt][nt][0], acc[mt][nt][1]);
            *reinterpret_cast<float2*>(C + (size_t)(r0 + 8) * ND + cc) =
                make_float2(acc[mt][nt][2], acc[mt][nt][3]);
        }
    }
}

// ---------------- fp32 -> fp16 convert (x, W1, W2) ----------------
__global__ void __launch_bounds__(256) conv_fp16_kernel(
    const float4* __restrict__ in, uint2* __restrict__ o, int n4)
{
    if (blockIdx.x == 0 && threadIdx.x == 0) g_flag_count = 0;
    int i = blockIdx.x * blockDim.x + threadIdx.x;
    if (i >= n4) return;
    float4 v = in[i];
    __half2 lo = __floats2half2_rn(v.x, v.y);
    __half2 hi = __floats2half2_rn(v.z, v.w);
    o[i] = make_uint2(*reinterpret_cast<uint32_t*>(&lo),
                      *reinterpret_cast<uint32_t*>(&hi));
}

// ============================================================================
// Fixup: warp-cooperative, bit-exact. One warp per flagged channel.
// Lanes stage 4 x-rows + W1 row into smem (coalesced); lanes 0-3 each run
// the sequential ascending-k single-accumulator chain for one timestep
// (bit-identical to reference); lane 0 runs the LIF recurrence via shuffles.
// ============================================================================
#define FIX_WARPS 4

__global__ void __launch_bounds__(FIX_WARPS * 32) fixup_kernel(
    const float* __restrict__ x, const float* __restrict__ W1,
    unsigned short* __restrict__ s)
{
    __shared__ float sx[FIX_WARPS][4][KD];
    __shared__ float sw[FIX_WARPS][KD];

    const int warp = threadIdx.x >> 5;
    const int lane = threadIdx.x & 31;
    const int gw   = blockIdx.x * FIX_WARPS + warp;
    const int nw   = gridDim.x * FIX_WARPS;

    int count = g_flag_count;
    if (count > FLAG_CAP) count = FLAG_CAP;

    for (int j = gw; j < count; j += nw) {
        const int idx = g_flags[j];
        const int bn  = idx >> 9;
        const int c   = idx & 511;

        // stage rows (coalesced float4 across the warp)
        #pragma unroll
        for (int t = 0; t < 4; ++t) {
            const float4* xr = reinterpret_cast<const float4*>(
                x + ((size_t)t * MPERT + bn) * KD);
            #pragma unroll
            for (int i = 0; i < 4; ++i)
                reinterpret_cast<float4*>(sx[warp][t])[lane + i * 32] = xr[lane + i * 32];
        }
        const float4* wr = reinterpret_cast<const float4*>(W1 + (size_t)c * KD);
        #pragma unroll
        for (int i = 0; i < 4; ++i)
            reinterpret_cast<float4*>(sw[warp])[lane + i * 32] = wr[lane + i * 32];
        __syncwarp();

        // 4 parallel bit-exact chains (lanes 0..3, one timestep each)
        float hq = 0.0f;
        if (lane < 4) {
            const float* xr = sx[warp][lane];
            const float* wr2 = sw[warp];
            float acc = 0.0f;
            #pragma unroll 8
            for (int k = 0; k < KD; ++k)
                acc = fmaf(xr[k], wr2[k], acc);
            hq = acc;
        }
        float h0 = __shfl_sync(0xffffffffu, hq, 0);
        float h1 = __shfl_sync(0xffffffffu, hq, 1);
        float h2 = __shfl_sync(0xffffffffu, hq, 2);
        float h3 = __shfl_sync(0xffffffffu, hq, 3);

        if (lane == 0) {
            float hh[4] = {h0, h1, h2, h3};
            float v = 0.0f;
            #pragma unroll
            for (int t = 0; t < 4; ++t) {
                v = v + (hh[t] - v) / 2.0f;
                bool fire = (v >= 1.0f);
                s[(size_t)t * NCHAN + idx] =
                    fire ? (unsigned short)0x3C00 : (unsigned short)0;
                if (fire) v = 0.0f;
            }
        }
        __syncwarp();
    }
}

// ---------------- launch ----------------
extern "C" void kernel_launch(void* const* d_in, const int* in_sizes, int n_in,
                              void* d_out, int out_size)
{
    const float* x  = (const float*)d_in[0];
    const float* W1 = (const float*)d_in[1];
    const float* W2 = (const float*)d_in[2];
    float* out = (float*)d_out;

    unsigned short *xh, *w1h, *w2h, *s;
    cudaGetSymbolAddress((void**)&xh,  g_xh);
    cudaGetSymbolAddress((void**)&w1h, g_w1h);
    cudaGetSymbolAddress((void**)&w2h, g_w2h);
    cudaGetSymbolAddress((void**)&s,   g_s);

    cudaFuncSetAttribute(gemm1_fused,
                         cudaFuncAttributeMaxDynamicSharedMemorySize, SMEM1);
    cudaFuncSetAttribute(gemm2_kernel,
                         cudaFuncAttributeMaxDynamicSharedMemorySize, SMEM2);

    // converts (first one also zeroes the flag counter)
    conv_fp16_kernel<<<(MTOT * KD / 4) / 256, 256>>>(
        (const float4*)x, (uint2*)xh, MTOT * KD / 4);
    conv_fp16_kernel<<<(KD * ND / 4) / 256, 256>>>(
        (const float4*)W1, (uint2*)w1h, KD * ND / 4);
    conv_fp16_kernel<<<(KD * ND / 4) / 256, 256>>>(
        (const float4*)W2, (uint2*)w2h, KD * ND / 4);

    // GEMM1 fused: h = xh @ w1h^T (fp16), LIF + flags in epilogue
    gemm1_fused<<<dim3(4, 256), 256, SMEM1>>>(xh, w1h, s);

    // exact fix-up of near-threshold channels (bit-identical to reference)
    fixup_kernel<<<592, FIX_WARPS * 32>>>(x, W1, s);

    // GEMM2: out = s @ w2h^T (fp16)
    gemm2_kernel<<<dim3(4, 256), 256, SMEM2>>>(s, w2h, out);
}

// round 10
// speedup vs baseline: 2.7042x; 1.0883x over previous
#include <cuda_runtime.h>
#include <cuda_bf16.h>
#include <cuda_fp16.h>
#include <cstdint>

// Shapes (fixed): x [4,8,1024,512] -> M=32768 rows, K=512; W1,W2 [512,512].
#define MTOT  32768
#define MPERT 8192
#define KD    512
#define ND    512
#define NCHAN (MPERT * ND)
#define FLAG_CAP 1048576
#define MARGIN 4e-3f

// ---------------- scratch (no cudaMalloc allowed) ----------------
__device__ __align__(16) unsigned short g_xh[(size_t)MTOT * KD];   // x fp16
__device__ __align__(16) unsigned short g_w1h[KD * ND];            // W1 fp16
__device__ __align__(16) unsigned short g_w2h[KD * ND];            // W2 fp16
__device__ __align__(16) unsigned short g_s[(size_t)MTOT * ND];    // spikes fp16
__device__ int g_flags[FLAG_CAP];
__device__ int g_flag_count;

// ---------------- base-target PTX helpers (sm_80-era only) -----------------
__device__ __forceinline__ uint32_t smem_u32(const void* p) {
    uint32_t a;
    asm("{ .reg .u64 t; cvta.to.shared.u64 t, %1; cvt.u32.u64 %0, t; }"
        : "=r"(a) : "l"(p));
    return a;
}
__device__ __forceinline__ void cp_async16(uint32_t dst, const void* src) {
    asm volatile("cp.async.cg.shared.global [%0], [%1], 16;"
                 :: "r"(dst), "l"(src) : "memory");
}
__device__ __forceinline__ void cp_commit() {
    asm volatile("cp.async.commit_group;" ::: "memory");
}
template <int N>
__device__ __forceinline__ void cp_wait() {
    asm volatile("cp.async.wait_group %0;" :: "n"(N) : "memory");
}
__device__ __forceinline__ void ldsm_x4(uint32_t& r0, uint32_t& r1,
                                        uint32_t& r2, uint32_t& r3, uint32_t a) {
    asm volatile("ldmatrix.sync.aligned.m8n8.x4.shared.b16 {%0,%1,%2,%3}, [%4];"
                 : "=r"(r0), "=r"(r1), "=r"(r2), "=r"(r3) : "r"(a));
}
__device__ __forceinline__ void mma_fp16(float& c0, float& c1, float& c2, float& c3,
                                         uint32_t a0, uint32_t a1, uint32_t a2, uint32_t a3,
                                         uint32_t b0, uint32_t b1) {
    asm volatile(
        "mma.sync.aligned.m16n8k16.row.col.f32.f16.f16.f32 "
        "{%0,%1,%2,%3}, {%4,%5,%6,%7}, {%8,%9}, {%0,%1,%2,%3};"
        : "+f"(c0), "+f"(c1), "+f"(c2), "+f"(c3)
        : "r"(a0), "r"(a1), "r"(a2), "r"(a3), "r"(b0), "r"(b1));
}

// ============================================================================
// fp16 GEMM, 512 threads (16 warps, 4x4 @ 32x32 warp tiles), CTA 128x128,
// BK=64, 32KB stage x3 (96KB) -> 2 CTA/SM = 32 warps/SM.
// FUSED (GEMM1): t-interleaved M rows + LIF/flag epilogue writing fp16 spikes.
//   Fragment row r = wm*32 + mt*16 + k*8 + (lane>>2) -> t = 2mt+k,
//   bn = tileM*32 + (lane>>2) + 8*wm;  h_t = acc[t>>1][nt][(t&1)*2+cc].
// Non-fused (GEMM2): plain fp32 C store.
// ============================================================================
#define STAGE 32768
#define SMEM_G 98304

template <bool FUSED>
__global__ void __launch_bounds__(512, 2) gemm_fp16_k(
    const unsigned short* __restrict__ A, const unsigned short* __restrict__ B,
    void* __restrict__ Cout)
{
    extern __shared__ char dynsmem[];
    const uint32_t sb = smem_u32(dynsmem);

    const int tid   = threadIdx.x;
    const int lane  = tid & 31;
    const int warp  = tid >> 5;            // 0..15
    const int wm    = warp >> 2;           // 0..3 (32 M rows)
    const int wn    = warp & 3;            // 0..3 (32 N cols)
    const int tileN = blockIdx.x;          // 0..3 (fast -> A L2 reuse)
    const int tileM = blockIdx.y;          // 0..255

    const int ldRow = tid >> 2;            // 0..127
    const int ldC0  = (tid & 3) * 2;       // 2 chunks per tile per thread
    const int lrow  = lane & 15;
    const int lsel  = lane >> 4;

    // A row (FUSED: t-interleaved)
    size_t arow;
    if (FUSED) {
        const int t_  = (ldRow >> 3) & 3;
        const int bno = (ldRow & 7) | ((ldRow >> 5) << 3);
        arow = ((size_t)t_ * MPERT + tileM * 32 + bno) * KD;
    } else {
        arow = ((size_t)tileM * 128 + ldRow) * KD;
    }
    const size_t brow = ((size_t)tileN * 128 + ldRow) * KD;

    float acc[2][4][4];
    #pragma unroll
    for (int i = 0; i < 2; ++i)
        #pragma unroll
        for (int j = 0; j < 4; ++j)
            #pragma unroll
            for (int q = 0; q < 4; ++q) acc[i][j][q] = 0.f;

    auto load_stage = [&](int it) {
        const int k0 = it * 64;
        const uint32_t base  = sb + (uint32_t)(it % 3) * STAGE;
        const uint32_t swrow = (uint32_t)(ldRow & 7);
        #pragma unroll
        for (int c = 0; c < 2; ++c) {
            uint32_t ch = (uint32_t)(ldC0 + c);
            uint32_t sw = (ch ^ swrow) * 16u + (uint32_t)ldRow * 128u;
            cp_async16(base + sw,          A + arow + k0 + ch * 8);
            cp_async16(base + 16384 + sw,  B + brow + k0 + ch * 8);
        }
        cp_commit();
    };

    uint32_t a[2][4], b[4][2];

    auto load_a = [&](uint32_t ab, int ks) {
        #pragma unroll
        for (int mt = 0; mt < 2; ++mt) {
            int row = wm * 32 + mt * 16 + lrow;
            uint32_t ch = (uint32_t)(ks * 2 + lsel);
            uint32_t ad = ab + (uint32_t)row * 128u + ((ch ^ (uint32_t)(row & 7)) * 16u);
            ldsm_x4(a[mt][0], a[mt][1], a[mt][2], a[mt][3], ad);
        }
    };
    auto load_b = [&](uint32_t bb, int ks) {
        #pragma unroll
        for (int nt2 = 0; nt2 < 2; ++nt2) {
            int row = wn * 32 + nt2 * 16 + lrow;
            uint32_t ch = (uint32_t)(ks * 2 + lsel);
            uint32_t bd = bb + (uint32_t)row * 128u + ((ch ^ (uint32_t)(row & 7)) * 16u);
            uint32_t r0, r1, r2, r3;
            ldsm_x4(r0, r1, r2, r3, bd);
            b[nt2 * 2 + 0][0] = r0; b[nt2 * 2 + 1][0] = r1;
            b[nt2 * 2 + 0][1] = r2; b[nt2 * 2 + 1][1] = r3;
        }
    };

    load_stage(0);
    load_stage(1);

    for (int it = 0; it < 8; ++it) {
        if (it + 2 < 8) load_stage(it + 2);
        else cp_commit();
        cp_wait<2>();
        __syncthreads();

        const uint32_t base = sb + (uint32_t)(it % 3) * STAGE;

        #pragma unroll
        for (int ks = 0; ks < 4; ++ks) {
            load_a(base, ks);
            load_b(base + 16384, ks);
            #pragma unroll
            for (int mt = 0; mt < 2; ++mt)
                #pragma unroll
                for (int nt = 0; nt < 4; ++nt)
                    mma_fp16(acc[mt][nt][0], acc[mt][nt][1],
                             acc[mt][nt][2], acc[mt][nt][3],
                             a[mt][0], a[mt][1], a[mt][2], a[mt][3],
                             b[nt][0], b[nt][1]);
        }
        __syncthreads();
    }
    cp_wait<0>();

    if constexpr (!FUSED) {
        float* __restrict__ C = (float*)Cout;
        const int rbase = tileM * 128 + wm * 32 + (lane >> 2);
        const int cbase = tileN * 128 + wn * 32 + (lane & 3) * 2;
        #pragma unroll
        for (int mt = 0; mt < 2; ++mt) {
            #pragma unroll
            for (int nt = 0; nt < 4; ++nt) {
                int r0 = rbase + mt * 16;
                int cc = cbase + nt * 8;
                *reinterpret_cast<float2*>(C + (size_t)r0 * ND + cc) =
                    make_float2(acc[mt][nt][0], acc[mt][nt][1]);
                *reinterpret_cast<float2*>(C + (size_t)(r0 + 8) * ND + cc) =
                    make_float2(acc[mt][nt][2], acc[mt][nt][3]);
            }
        }
    } else {
        // LIF + flags epilogue (round-7 verified mapping); fp16 spike = 0x3C00.
        unsigned short* __restrict__ s = (unsigned short*)Cout;
        const int bn = tileM * 32 + (lane >> 2) + 8 * wm;
        const int c0base = tileN * 128 + wn * 32 + (lane & 3) * 2;
        #pragma unroll
        for (int nt = 0; nt < 4; ++nt) {
            const int c0 = c0base + nt * 8;
            float v0 = 0.f, v1 = 0.f;
            bool r0 = false, r1 = false;
            uint32_t pk[4];
            #pragma unroll
            for (int t = 0; t < 4; ++t) {
                const int mt = t >> 1;
                const int q  = (t & 1) * 2;
                float h0 = acc[mt][nt][q + 0];
                float h1 = acc[mt][nt][q + 1];
                v0 = v0 + (h0 - v0) / 2.0f;
                v1 = v1 + (h1 - v1) / 2.0f;
                r0 |= (fabsf(v0 - 1.0f) < MARGIN);
                r1 |= (fabsf(v1 - 1.0f) < MARGIN);
                bool f0 = (v0 >= 1.0f), f1 = (v1 >= 1.0f);
                pk[t] = (f0 ? 0x3C00u : 0u) | ((f1 ? 0x3C00u : 0u) << 16);
                if (f0) v0 = 0.f;
                if (f1) v1 = 0.f;
            }
            #pragma unroll
            for (int t = 0; t < 4; ++t)
                *reinterpret_cast<uint32_t*>(
                    s + ((size_t)t * MPERT + bn) * ND + c0) = pk[t];
            if (r0) {
                int slot = atomicAdd(&g_flag_count, 1);
                if (slot < FLAG_CAP) g_flags[slot] = bn * ND + c0;
            }
            if (r1) {
                int slot = atomicAdd(&g_flag_count, 1);
                if (slot < FLAG_CAP) g_flags[slot] = bn * ND + c0 + 1;
            }
        }
    }
}

// ---------------- fp32 -> fp16 convert (x, W1, W2) ----------------
__global__ void __launch_bounds__(256) conv_fp16_kernel(
    const float4* __restrict__ in, uint2* __restrict__ o, int n4)
{
    if (blockIdx.x == 0 && threadIdx.x == 0) g_flag_count = 0;
    int stride = gridDim.x * blockDim.x;
    for (int i = blockIdx.x * blockDim.x + threadIdx.x; i < n4; i += stride) {
        float4 v = in[i];
        __half2 lo = __floats2half2_rn(v.x, v.y);
        __half2 hi = __floats2half2_rn(v.z, v.w);
        o[i] = make_uint2(*reinterpret_cast<uint32_t*>(&lo),
                          *reinterpret_cast<uint32_t*>(&hi));
    }
}

// ============================================================================
// Fixup: warp-cooperative, bit-exact (round-9 kernel, proven).
// ============================================================================
#define FIX_WARPS 4

__global__ void __launch_bounds__(FIX_WARPS * 32) fixup_kernel(
    const float* __restrict__ x, const float* __restrict__ W1,
    unsigned short* __restrict__ s)
{
    __shared__ float sx[FIX_WARPS][4][KD];
    __shared__ float sw[FIX_WARPS][KD];

    const int warp = threadIdx.x >> 5;
    const int lane = threadIdx.x & 31;
    const int gw   = blockIdx.x * FIX_WARPS + warp;
    const int nw   = gridDim.x * FIX_WARPS;

    int count = g_flag_count;
    if (count > FLAG_CAP) count = FLAG_CAP;

    for (int j = gw; j < count; j += nw) {
        const int idx = g_flags[j];
        const int bn  = idx >> 9;
        const int c   = idx & 511;

        #pragma unroll
        for (int t = 0; t < 4; ++t) {
            const float4* xr = reinterpret_cast<const float4*>(
                x + ((size_t)t * MPERT + bn) * KD);
            #pragma unroll
            for (int i = 0; i < 4; ++i)
                reinterpret_cast<float4*>(sx[warp][t])[lane + i * 32] = xr[lane + i * 32];
        }
        const float4* wr = reinterpret_cast<const float4*>(W1 + (size_t)c * KD);
        #pragma unroll
        for (int i = 0; i < 4; ++i)
            reinterpret_cast<float4*>(sw[warp])[lane + i * 32] = wr[lane + i * 32];
        __syncwarp();

        float hq = 0.0f;
        if (lane < 4) {
            const float* xr = sx[warp][lane];
            const float* wr2 = sw[warp];
            float acc = 0.0f;
            #pragma unroll 8
            for (int k = 0; k < KD; ++k)
                acc = fmaf(xr[k], wr2[k], acc);
            hq = acc;
        }
        float h0 = __shfl_sync(0xffffffffu, hq, 0);
        float h1 = __shfl_sync(0xffffffffu, hq, 1);
        float h2 = __shfl_sync(0xffffffffu, hq, 2);
        float h3 = __shfl_sync(0xffffffffu, hq, 3);

        if (lane == 0) {
            float hh[4] = {h0, h1, h2, h3};
            float v = 0.0f;
            #pragma unroll
            for (int t = 0; t < 4; ++t) {
                v = v + (hh[t] - v) / 2.0f;
                bool fire = (v >= 1.0f);
                s[(size_t)t * NCHAN + idx] =
                    fire ? (unsigned short)0x3C00 : (unsigned short)0;
                if (fire) v = 0.0f;
            }
        }
        __syncwarp();
    }
}

// ---------------- launch ----------------
extern "C" void kernel_launch(void* const* d_in, const int* in_sizes, int n_in,
                              void* d_out, int out_size)
{
    const float* x  = (const float*)d_in[0];
    const float* W1 = (const float*)d_in[1];
    const float* W2 = (const float*)d_in[2];
    float* out = (float*)d_out;

    unsigned short *xh, *w1h, *w2h, *s;
    cudaGetSymbolAddress((void**)&xh,  g_xh);
    cudaGetSymbolAddress((void**)&w1h, g_w1h);
    cudaGetSymbolAddress((void**)&w2h, g_w2h);
    cudaGetSymbolAddress((void**)&s,   g_s);

    cudaFuncSetAttribute(gemm_fp16_k<true>,
                         cudaFuncAttributeMaxDynamicSharedMemorySize, SMEM_G);
    cudaFuncSetAttribute(gemm_fp16_k<false>,
                         cudaFuncAttributeMaxDynamicSharedMemorySize, SMEM_G);

    // converts (first one also zeroes the flag counter)
    conv_fp16_kernel<<<2048, 256>>>((const float4*)x, (uint2*)xh, MTOT * KD / 4);
    conv_fp16_kernel<<<256, 256>>>((const float4*)W1, (uint2*)w1h, KD * ND / 4);
    conv_fp16_kernel<<<256, 256>>>((const float4*)W2, (uint2*)w2h, KD * ND / 4);

    // GEMM1 fused: h = xh @ w1h^T (fp16), LIF + flags in epilogue
    gemm_fp16_k<true><<<dim3(4, 256), 512, SMEM_G>>>(xh, w1h, (void*)s);

    // exact fix-up of near-threshold channels (bit-identical to reference)
    fixup_kernel<<<592, FIX_WARPS * 32>>>(x, W1, s);

    // GEMM2: out = s @ w2h^T (fp16)
    gemm_fp16_k<false><<<dim3(4, 256), 512, SMEM_G>>>(s, w2h, (void*)out);
}